// round 6
// baseline (speedup 1.0000x reference)
#include <cuda_runtime.h>
#include <math.h>

// Proven structure: identical grid + grid-stride mapping in both kernels.
// Pass A reads stripes ascending (default-cached -> tail stays in L2);
// Pass B reads stripes DESCENDING (first reads hit that resident tail).
// This round: all-32-bit indexing (nvec < 2^31) to cut regs/ALU and restore
// occupancy that R5's 64-bit index math destroyed (regs 40 -> target <=32).
#define NCTA 2368          // 148 SMs * 16 CTAs
#define THREADS 256

__device__ float g_partials[NCTA];

__device__ __forceinline__ float block_reduce_max(float m) {
    #pragma unroll
    for (int o = 16; o > 0; o >>= 1)
        m = fmaxf(m, __shfl_xor_sync(0xffffffffu, m, o));
    __shared__ float sm[THREADS / 32];
    int lane = threadIdx.x & 31;
    int w = threadIdx.x >> 5;
    if (lane == 0) sm[w] = m;
    __syncthreads();
    if (w == 0) {
        m = (lane < (THREADS / 32)) ? sm[lane] : 0.0f;
        #pragma unroll
        for (int o = 16; o > 0; o >>= 1)
            m = fmaxf(m, __shfl_xor_sync(0xffffffffu, m, o));
    }
    return m;  // valid in warp 0
}

__device__ __forceinline__ void stcs4(float4* p, float4 v) {
    asm volatile("st.global.cs.v4.f32 [%0], {%1,%2,%3,%4};"
                 :: "l"(p), "f"(v.x), "f"(v.y), "f"(v.z), "f"(v.w) : "memory");
}

__device__ __forceinline__ float max4(float4 v) {
    return fmaxf(fmaxf(fabsf(v.x), fabsf(v.y)), fmaxf(fabsf(v.z), fabsf(v.w)));
}

// Pass A: global max|x|, ascending grid-stride, default-cached loads.
__global__ void __launch_bounds__(THREADS)
bq_max_reduce_kernel(const float4* __restrict__ x, unsigned nvec,
                     const float* __restrict__ xs, unsigned ntail_base, unsigned ntail) {
    float m = 0.0f;
    const unsigned stride = gridDim.x * THREADS;
    for (unsigned i = blockIdx.x * THREADS + threadIdx.x; i < nvec; i += stride)
        m = fmaxf(m, max4(x[i]));

    if (blockIdx.x == 0 && threadIdx.x < ntail)
        m = fmaxf(m, fabsf(xs[ntail_base + threadIdx.x]));

    m = block_reduce_max(m);
    if (threadIdx.x == 0)
        g_partials[blockIdx.x] = m;
}

__device__ __forceinline__ float bq_quant_one(float v, float s, float inv_s) {
    v = (v >= 0.0f) ? fmaxf(v, 1e-10f) : fminf(v, -1e-10f);  // zeros -> +1e-10
    float i = rintf(v * s);                                   // half-to-even
    i = fminf(fmaxf(i, -128.0f), 127.0f);                     // clip to int8 range
    return i * inv_s;                                         // exact pow2 scale
}

__device__ __forceinline__ float4 quant4(float4 v, float s, float inv_s) {
    v.x = bq_quant_one(v.x, s, inv_s);
    v.y = bq_quant_one(v.y, s, inv_s);
    v.z = bq_quant_one(v.z, s, inv_s);
    v.w = bq_quant_one(v.w, s, inv_s);
    return v;
}

// Pass B: prologue reduces the (L2-resident) partials, then quantize stripes
// in DESCENDING order. x reads default-cached (hit pass A's hot tail);
// y stores evict-first so write-allocate doesn't displace it.
__global__ void __launch_bounds__(THREADS)
bq_quantize_kernel(const float4* __restrict__ x, float4* __restrict__ y,
                   unsigned nvec,
                   const float* __restrict__ xs, float* __restrict__ ys,
                   unsigned ntail_base, unsigned ntail) {
    __shared__ float s_sc[2];
    {
        float m = 0.0f;
        for (unsigned p = threadIdx.x; p < NCTA; p += THREADS)
            m = fmaxf(m, g_partials[p]);
        m = block_reduce_max(m);
        if (threadIdx.x == 0) {
            float maxv = fmaxf(m, 1e-10f);  // the 1e-10 clamp can only raise tiny maxima
            float e = floorf(log2f(maxv));
            e = fminf(fmaxf(e, -128.0f), 127.0f);
            s_sc[0] = exp2f(-e + 6.0f);     // 2^(-e + (bits-2)), bits=8
            s_sc[1] = exp2f(e - 6.0f);
        }
    }
    __syncthreads();
    const float s = s_sc[0], inv_s = s_sc[1];

    const unsigned stride = gridDim.x * THREADS;
    const unsigned i0 = blockIdx.x * THREADS + threadIdx.x;
    if (i0 < nvec) {
        // one udiv at entry, then a pure decrement loop (all 32-bit)
        unsigned i = i0 + ((nvec - 1 - i0) / stride) * stride;
        for (;;) {
            stcs4(&y[i], quant4(x[i], s, inv_s));
            if (i == i0) break;
            i -= stride;
        }
    }

    if (blockIdx.x == 0 && threadIdx.x < ntail)
        ys[ntail_base + threadIdx.x] =
            bq_quant_one(xs[ntail_base + threadIdx.x], s, inv_s);
}

extern "C" void kernel_launch(void* const* d_in, const int* in_sizes, int n_in,
                              void* d_out, int out_size) {
    const float* x = (const float*)d_in[0];
    float* y = (float*)d_out;
    unsigned n = (unsigned)in_sizes[0];
    unsigned nvec = n >> 2;
    unsigned ntail_base = nvec << 2;
    unsigned ntail = n - ntail_base;

    bq_max_reduce_kernel<<<NCTA, THREADS>>>(
        (const float4*)x, nvec, x, ntail_base, ntail);

    bq_quantize_kernel<<<NCTA, THREADS>>>(
        (const float4*)x, (float4*)y, nvec, x, y, ntail_base, ntail);
}

// round 7
// speedup vs baseline: 1.0021x; 1.0021x over previous
#include <cuda_runtime.h>
#include <math.h>

// ONE persistent kernel: phase 1 (global max reduce, ascending stripes) ->
// grid-wide ticket barrier -> phase 2 (quantize, descending stripes; first
// reads hit the L2 tail phase 1 just left hot). Grid = exactly one wave
// (148 SMs x 8 CTAs of 256 thr = 2048 thr/SM) so all CTAs are co-resident
// and the barrier cannot deadlock. The ticket counter only ever increases ->
// deterministic under graph replay, no reset pass.
#define NCTA 1184
#define THREADS 256

__device__ float g_partials[NCTA];
__device__ unsigned g_ticket;   // zero-init; grows by NCTA per replay

__device__ __forceinline__ float block_reduce_max(float m) {
    #pragma unroll
    for (int o = 16; o > 0; o >>= 1)
        m = fmaxf(m, __shfl_xor_sync(0xffffffffu, m, o));
    __shared__ float sm[THREADS / 32];
    int lane = threadIdx.x & 31;
    int w = threadIdx.x >> 5;
    if (lane == 0) sm[w] = m;
    __syncthreads();
    if (w == 0) {
        m = (lane < (THREADS / 32)) ? sm[lane] : 0.0f;
        #pragma unroll
        for (int o = 16; o > 0; o >>= 1)
            m = fmaxf(m, __shfl_xor_sync(0xffffffffu, m, o));
    }
    return m;  // valid in warp 0
}

__device__ __forceinline__ void stcs4(float4* p, float4 v) {
    asm volatile("st.global.cs.v4.f32 [%0], {%1,%2,%3,%4};"
                 :: "l"(p), "f"(v.x), "f"(v.y), "f"(v.z), "f"(v.w) : "memory");
}

__device__ __forceinline__ float max4(float4 v) {
    return fmaxf(fmaxf(fabsf(v.x), fabsf(v.y)), fmaxf(fabsf(v.z), fabsf(v.w)));
}

__device__ __forceinline__ float bq_quant_one(float v, float s, float inv_s) {
    v = (v >= 0.0f) ? fmaxf(v, 1e-10f) : fminf(v, -1e-10f);  // zeros -> +1e-10
    float i = rintf(v * s);                                   // half-to-even
    i = fminf(fmaxf(i, -128.0f), 127.0f);                     // clip to int8 range
    return i * inv_s;                                         // exact pow2 scale
}

__device__ __forceinline__ float4 quant4(float4 v, float s, float inv_s) {
    v.x = bq_quant_one(v.x, s, inv_s);
    v.y = bq_quant_one(v.y, s, inv_s);
    v.z = bq_quant_one(v.z, s, inv_s);
    v.w = bq_quant_one(v.w, s, inv_s);
    return v;
}

__global__ void __launch_bounds__(THREADS, 8)
bq_fused_kernel(const float4* __restrict__ x, float4* __restrict__ y,
                unsigned nvec,
                const float* __restrict__ xs, float* __restrict__ ys,
                unsigned ntail_base, unsigned ntail) {
    const unsigned stride = NCTA * THREADS;
    const unsigned i0 = blockIdx.x * THREADS + threadIdx.x;

    // ---- Phase 1: max |x| over ascending grid-stride stripes ----
    float m = 0.0f;
    for (unsigned i = i0; i < nvec; i += stride)
        m = fmaxf(m, max4(x[i]));
    if (blockIdx.x == 0 && threadIdx.x < ntail)
        m = fmaxf(m, fabsf(xs[ntail_base + threadIdx.x]));
    m = block_reduce_max(m);

    // ---- Grid barrier (ticket-based, replay-safe, no reset) ----
    if (threadIdx.x == 0) {
        g_partials[blockIdx.x] = m;
        __threadfence();                      // release partial before arriving
        unsigned t = atomicAdd(&g_ticket, 1u);
        unsigned target = (t / NCTA + 1u) * NCTA;
        for (;;) {
            unsigned cur;
            asm volatile("ld.global.acquire.gpu.u32 %0, [%1];"
                         : "=r"(cur) : "l"(&g_ticket));
            if (cur >= target) break;
            __nanosleep(64);
        }
    }
    __syncthreads();                          // propagates t0's acquire CTA-wide

    // ---- Scale computation (partials are L2-resident; ldcg avoids L1) ----
    __shared__ float s_sc[2];
    {
        float mm = 0.0f;
        for (unsigned p = threadIdx.x; p < NCTA; p += THREADS)
            mm = fmaxf(mm, __ldcg(&g_partials[p]));
        mm = block_reduce_max(mm);
        if (threadIdx.x == 0) {
            float maxv = fmaxf(mm, 1e-10f);   // 1e-10 clamp can only raise tiny maxima
            float e = floorf(log2f(maxv));
            e = fminf(fmaxf(e, -128.0f), 127.0f);
            s_sc[0] = exp2f(-e + 6.0f);       // 2^(-e + (bits-2)), bits=8
            s_sc[1] = exp2f(e - 6.0f);
        }
    }
    __syncthreads();
    const float s = s_sc[0], inv_s = s_sc[1];

    // ---- Phase 2: quantize, descending stripes (hit phase 1's hot L2 tail);
    //      evict-first stores keep the output from displacing it ----
    if (i0 < nvec) {
        unsigned i = i0 + ((nvec - 1u - i0) / stride) * stride;
        for (;;) {
            stcs4(&y[i], quant4(x[i], s, inv_s));
            if (i == i0) break;
            i -= stride;
        }
    }
    if (blockIdx.x == 0 && threadIdx.x < ntail)
        ys[ntail_base + threadIdx.x] =
            bq_quant_one(xs[ntail_base + threadIdx.x], s, inv_s);
}

extern "C" void kernel_launch(void* const* d_in, const int* in_sizes, int n_in,
                              void* d_out, int out_size) {
    const float* x = (const float*)d_in[0];
    float* y = (float*)d_out;
    unsigned n = (unsigned)in_sizes[0];
    unsigned nvec = n >> 2;
    unsigned ntail_base = nvec << 2;
    unsigned ntail = n - ntail_base;

    bq_fused_kernel<<<NCTA, THREADS>>>(
        (const float4*)x, (float4*)y, nvec, x, y, ntail_base, ntail);
}

// round 8
// speedup vs baseline: 1.0029x; 1.0008x over previous
#include <cuda_runtime.h>
#include <math.h>

// ONE persistent kernel: phase 1 (global max reduce, ascending stripes) ->
// grid-wide ticket barrier -> phase 2 (quantize, descending stripes).
// Grid = exactly one wave (148 SMs x 8 CTAs x 256 thr) so all CTAs are
// co-resident and the barrier cannot deadlock. Ticket counter only grows ->
// deterministic under graph replay, no reset pass.
//
// R8 change: y stores are WRITE-THROUGH (st.global.wt). No dirty y-lines are
// left in L2 at kernel end, so the NEXT replay's phase 1 is a pure-read
// stream (no eviction write-backs mixed into its reads). ncu showed this
// kernel at 240us with a clean L2; steady-state replay should now match.
#define NCTA 1184
#define THREADS 256

__device__ float g_partials[NCTA];
__device__ unsigned g_ticket;   // zero-init; grows by NCTA per replay

__device__ __forceinline__ float block_reduce_max(float m) {
    #pragma unroll
    for (int o = 16; o > 0; o >>= 1)
        m = fmaxf(m, __shfl_xor_sync(0xffffffffu, m, o));
    __shared__ float sm[THREADS / 32];
    int lane = threadIdx.x & 31;
    int w = threadIdx.x >> 5;
    if (lane == 0) sm[w] = m;
    __syncthreads();
    if (w == 0) {
        m = (lane < (THREADS / 32)) ? sm[lane] : 0.0f;
        #pragma unroll
        for (int o = 16; o > 0; o >>= 1)
            m = fmaxf(m, __shfl_xor_sync(0xffffffffu, m, o));
    }
    return m;  // valid in warp 0
}

__device__ __forceinline__ void stwt4(float4* p, float4 v) {
    asm volatile("st.global.wt.v4.f32 [%0], {%1,%2,%3,%4};"
                 :: "l"(p), "f"(v.x), "f"(v.y), "f"(v.z), "f"(v.w) : "memory");
}

__device__ __forceinline__ float max4(float4 v) {
    return fmaxf(fmaxf(fabsf(v.x), fabsf(v.y)), fmaxf(fabsf(v.z), fabsf(v.w)));
}

__device__ __forceinline__ float bq_quant_one(float v, float s, float inv_s) {
    v = (v >= 0.0f) ? fmaxf(v, 1e-10f) : fminf(v, -1e-10f);  // zeros -> +1e-10
    float i = rintf(v * s);                                   // half-to-even
    i = fminf(fmaxf(i, -128.0f), 127.0f);                     // clip to int8 range
    return i * inv_s;                                         // exact pow2 scale
}

__device__ __forceinline__ float4 quant4(float4 v, float s, float inv_s) {
    v.x = bq_quant_one(v.x, s, inv_s);
    v.y = bq_quant_one(v.y, s, inv_s);
    v.z = bq_quant_one(v.z, s, inv_s);
    v.w = bq_quant_one(v.w, s, inv_s);
    return v;
}

__global__ void __launch_bounds__(THREADS, 8)
bq_fused_kernel(const float4* __restrict__ x, float4* __restrict__ y,
                unsigned nvec,
                const float* __restrict__ xs, float* __restrict__ ys,
                unsigned ntail_base, unsigned ntail) {
    const unsigned stride = NCTA * THREADS;
    const unsigned i0 = blockIdx.x * THREADS + threadIdx.x;

    // ---- Phase 1: max |x| over ascending grid-stride stripes (pure reads) ----
    float m = 0.0f;
    for (unsigned i = i0; i < nvec; i += stride)
        m = fmaxf(m, max4(x[i]));
    if (blockIdx.x == 0 && threadIdx.x < ntail)
        m = fmaxf(m, fabsf(xs[ntail_base + threadIdx.x]));
    m = block_reduce_max(m);

    // ---- Grid barrier (ticket-based, replay-safe, no reset) ----
    if (threadIdx.x == 0) {
        g_partials[blockIdx.x] = m;
        __threadfence();                      // release partial before arriving
        unsigned t = atomicAdd(&g_ticket, 1u);
        unsigned target = (t / NCTA + 1u) * NCTA;
        for (;;) {
            unsigned cur;
            asm volatile("ld.global.acquire.gpu.u32 %0, [%1];"
                         : "=r"(cur) : "l"(&g_ticket));
            if (cur >= target) break;
            __nanosleep(64);
        }
    }
    __syncthreads();                          // propagates t0's acquire CTA-wide

    // ---- Scale computation (partials are L2-resident) ----
    __shared__ float s_sc[2];
    {
        float mm = 0.0f;
        for (unsigned p = threadIdx.x; p < NCTA; p += THREADS)
            mm = fmaxf(mm, __ldcg(&g_partials[p]));
        mm = block_reduce_max(mm);
        if (threadIdx.x == 0) {
            float maxv = fmaxf(mm, 1e-10f);   // 1e-10 clamp can only raise tiny maxima
            float e = floorf(log2f(maxv));
            e = fminf(fmaxf(e, -128.0f), 127.0f);
            s_sc[0] = exp2f(-e + 6.0f);       // 2^(-e + (bits-2)), bits=8
            s_sc[1] = exp2f(e - 6.0f);
        }
    }
    __syncthreads();
    const float s = s_sc[0], inv_s = s_sc[1];

    // ---- Phase 2: quantize, descending stripes (hit phase 1's hot L2 tail);
    //      write-through stores leave L2 clean for the next replay ----
    if (i0 < nvec) {
        unsigned i = i0 + ((nvec - 1u - i0) / stride) * stride;
        for (;;) {
            stwt4(&y[i], quant4(x[i], s, inv_s));
            if (i == i0) break;
            i -= stride;
        }
    }
    if (blockIdx.x == 0 && threadIdx.x < ntail)
        ys[ntail_base + threadIdx.x] =
            bq_quant_one(xs[ntail_base + threadIdx.x], s, inv_s);
}

extern "C" void kernel_launch(void* const* d_in, const int* in_sizes, int n_in,
                              void* d_out, int out_size) {
    const float* x = (const float*)d_in[0];
    float* y = (float*)d_out;
    unsigned n = (unsigned)in_sizes[0];
    unsigned nvec = n >> 2;
    unsigned ntail_base = nvec << 2;
    unsigned ntail = n - ntail_base;

    bq_fused_kernel<<<NCTA, THREADS>>>(
        (const float4*)x, (float4*)y, nvec, x, y, ntail_base, ntail);
}

// round 9
// speedup vs baseline: 1.0089x; 1.0060x over previous
#include <cuda_runtime.h>
#include <math.h>

// Consolidated best-measured configuration (roofline form):
//  - split two-kernel: reduce -> quantize (best harness steady-state)
//  - 2368 CTAs, ascending grid-stride float4 streaming in both kernels
//  - plain (default) loads and stores: every cache-hint variant benched <= neutral
//  - write-always partials array: no reset kernel, no atomics, replay-deterministic
//  - 32-bit indexing throughout (25 regs, ~94% occupancy)
// Both phases run at the chip's flat ~6.3 TB/s streaming ceiling (LTS/DRAM cap,
// path-independent) -> device floor ~= 1.5GB / 6.3TB/s ~= 240us.
#define NCTA 2368          // 148 SMs * 16 CTAs
#define THREADS 256

__device__ float g_partials[NCTA];

__device__ __forceinline__ float block_reduce_max(float m) {
    #pragma unroll
    for (int o = 16; o > 0; o >>= 1)
        m = fmaxf(m, __shfl_xor_sync(0xffffffffu, m, o));
    __shared__ float sm[THREADS / 32];
    int lane = threadIdx.x & 31;
    int w = threadIdx.x >> 5;
    if (lane == 0) sm[w] = m;
    __syncthreads();
    if (w == 0) {
        m = (lane < (THREADS / 32)) ? sm[lane] : 0.0f;
        #pragma unroll
        for (int o = 16; o > 0; o >>= 1)
            m = fmaxf(m, __shfl_xor_sync(0xffffffffu, m, o));
    }
    return m;  // valid in warp 0
}

__device__ __forceinline__ float max4(float4 v) {
    return fmaxf(fmaxf(fabsf(v.x), fabsf(v.y)), fmaxf(fabsf(v.z), fabsf(v.w)));
}

// Pass A: global max|x|, ascending grid-stride streaming.
__global__ void __launch_bounds__(THREADS)
bq_max_reduce_kernel(const float4* __restrict__ x, unsigned nvec,
                     const float* __restrict__ xs, unsigned ntail_base, unsigned ntail) {
    float m = 0.0f;
    const unsigned stride = NCTA * THREADS;
    for (unsigned i = blockIdx.x * THREADS + threadIdx.x; i < nvec; i += stride)
        m = fmaxf(m, max4(x[i]));

    if (blockIdx.x == 0 && threadIdx.x < ntail)
        m = fmaxf(m, fabsf(xs[ntail_base + threadIdx.x]));

    m = block_reduce_max(m);
    if (threadIdx.x == 0)
        g_partials[blockIdx.x] = m;
}

__device__ __forceinline__ float bq_quant_one(float v, float s, float inv_s) {
    v = (v >= 0.0f) ? fmaxf(v, 1e-10f) : fminf(v, -1e-10f);  // zeros -> +1e-10
    float i = rintf(v * s);                                   // half-to-even
    i = fminf(fmaxf(i, -128.0f), 127.0f);                     // clip to int8 range
    return i * inv_s;                                         // exact pow2 scale
}

__device__ __forceinline__ float4 quant4(float4 v, float s, float inv_s) {
    v.x = bq_quant_one(v.x, s, inv_s);
    v.y = bq_quant_one(v.y, s, inv_s);
    v.z = bq_quant_one(v.z, s, inv_s);
    v.w = bq_quant_one(v.w, s, inv_s);
    return v;
}

// Pass B: prologue reduces the (L2-resident) partials, then ascending
// grid-stride quantize stream.
__global__ void __launch_bounds__(THREADS)
bq_quantize_kernel(const float4* __restrict__ x, float4* __restrict__ y,
                   unsigned nvec,
                   const float* __restrict__ xs, float* __restrict__ ys,
                   unsigned ntail_base, unsigned ntail) {
    __shared__ float s_sc[2];
    {
        float m = 0.0f;
        for (unsigned p = threadIdx.x; p < NCTA; p += THREADS)
            m = fmaxf(m, g_partials[p]);
        m = block_reduce_max(m);
        if (threadIdx.x == 0) {
            float maxv = fmaxf(m, 1e-10f);  // the 1e-10 clamp can only raise tiny maxima
            float e = floorf(log2f(maxv));
            e = fminf(fmaxf(e, -128.0f), 127.0f);
            s_sc[0] = exp2f(-e + 6.0f);     // 2^(-e + (bits-2)), bits=8
            s_sc[1] = exp2f(e - 6.0f);
        }
    }
    __syncthreads();
    const float s = s_sc[0], inv_s = s_sc[1];

    const unsigned stride = NCTA * THREADS;
    for (unsigned i = blockIdx.x * THREADS + threadIdx.x; i < nvec; i += stride)
        y[i] = quant4(x[i], s, inv_s);

    if (blockIdx.x == 0 && threadIdx.x < ntail)
        ys[ntail_base + threadIdx.x] =
            bq_quant_one(xs[ntail_base + threadIdx.x], s, inv_s);
}

extern "C" void kernel_launch(void* const* d_in, const int* in_sizes, int n_in,
                              void* d_out, int out_size) {
    const float* x = (const float*)d_in[0];
    float* y = (float*)d_out;
    unsigned n = (unsigned)in_sizes[0];
    unsigned nvec = n >> 2;
    unsigned ntail_base = nvec << 2;
    unsigned ntail = n - ntail_base;

    bq_max_reduce_kernel<<<NCTA, THREADS>>>(
        (const float4*)x, nvec, x, ntail_base, ntail);

    bq_quantize_kernel<<<NCTA, THREADS>>>(
        (const float4*)x, (float4*)y, nvec, x, y, ntail_base, ntail);
}

// round 10
// speedup vs baseline: 1.0094x; 1.0005x over previous
#include <cuda_runtime.h>
#include <math.h>

// Split two-kernel roofline form. Quantize pass untouched (pinned at its mixed
// R/W ceiling ~6.3 TB/s across 9 rounds). This round targets the REDUCE pass:
// explicit 4x front-batched independent float4 loads per iteration to raise
// per-warp MLP (grid-stride loops unroll poorly -> MLP~1 -> latency-bound at
// ~6.1 TB/s; a pure-read stream has headroom to ~7.5 TB/s before HBM binds).
#define NCTA 2368          // 148 SMs * 16 CTAs
#define THREADS 256

__device__ float g_partials[NCTA];

__device__ __forceinline__ float block_reduce_max(float m) {
    #pragma unroll
    for (int o = 16; o > 0; o >>= 1)
        m = fmaxf(m, __shfl_xor_sync(0xffffffffu, m, o));
    __shared__ float sm[THREADS / 32];
    int lane = threadIdx.x & 31;
    int w = threadIdx.x >> 5;
    if (lane == 0) sm[w] = m;
    __syncthreads();
    if (w == 0) {
        m = (lane < (THREADS / 32)) ? sm[lane] : 0.0f;
        #pragma unroll
        for (int o = 16; o > 0; o >>= 1)
            m = fmaxf(m, __shfl_xor_sync(0xffffffffu, m, o));
    }
    return m;  // valid in warp 0
}

__device__ __forceinline__ float max4(float4 v) {
    return fmaxf(fmaxf(fabsf(v.x), fabsf(v.y)), fmaxf(fabsf(v.z), fabsf(v.w)));
}

// Pass A: global max|x|. 4 independent front-batched LDG.128 per iteration.
__global__ void __launch_bounds__(THREADS)
bq_max_reduce_kernel(const float4* __restrict__ x, unsigned nvec,
                     const float* __restrict__ xs, unsigned ntail_base, unsigned ntail) {
    const unsigned stride = NCTA * THREADS;
    unsigned i = blockIdx.x * THREADS + threadIdx.x;

    float m0 = 0.0f, m1 = 0.0f, m2 = 0.0f, m3 = 0.0f;
    // main loop: 4 independent loads issued back-to-back (MLP >= 4),
    // accumulated into 4 separate maxima (no serializing dependence).
    for (; i + 3u * stride < nvec; i += 4u * stride) {
        float4 a = x[i];
        float4 b = x[i + stride];
        float4 c = x[i + 2u * stride];
        float4 d = x[i + 3u * stride];
        m0 = fmaxf(m0, max4(a));
        m1 = fmaxf(m1, max4(b));
        m2 = fmaxf(m2, max4(c));
        m3 = fmaxf(m3, max4(d));
    }
    for (; i < nvec; i += stride)
        m0 = fmaxf(m0, max4(x[i]));

    float m = fmaxf(fmaxf(m0, m1), fmaxf(m2, m3));

    if (blockIdx.x == 0 && threadIdx.x < ntail)
        m = fmaxf(m, fabsf(xs[ntail_base + threadIdx.x]));

    m = block_reduce_max(m);
    if (threadIdx.x == 0)
        g_partials[blockIdx.x] = m;
}

__device__ __forceinline__ float bq_quant_one(float v, float s, float inv_s) {
    v = (v >= 0.0f) ? fmaxf(v, 1e-10f) : fminf(v, -1e-10f);  // zeros -> +1e-10
    float i = rintf(v * s);                                   // half-to-even
    i = fminf(fmaxf(i, -128.0f), 127.0f);                     // clip to int8 range
    return i * inv_s;                                         // exact pow2 scale
}

__device__ __forceinline__ float4 quant4(float4 v, float s, float inv_s) {
    v.x = bq_quant_one(v.x, s, inv_s);
    v.y = bq_quant_one(v.y, s, inv_s);
    v.z = bq_quant_one(v.z, s, inv_s);
    v.w = bq_quant_one(v.w, s, inv_s);
    return v;
}

// Pass B: prologue reduces the (L2-resident) partials, then ascending
// grid-stride quantize stream. UNCHANGED from R9 (at its ceiling).
__global__ void __launch_bounds__(THREADS)
bq_quantize_kernel(const float4* __restrict__ x, float4* __restrict__ y,
                   unsigned nvec,
                   const float* __restrict__ xs, float* __restrict__ ys,
                   unsigned ntail_base, unsigned ntail) {
    __shared__ float s_sc[2];
    {
        float m = 0.0f;
        for (unsigned p = threadIdx.x; p < NCTA; p += THREADS)
            m = fmaxf(m, g_partials[p]);
        m = block_reduce_max(m);
        if (threadIdx.x == 0) {
            float maxv = fmaxf(m, 1e-10f);  // the 1e-10 clamp can only raise tiny maxima
            float e = floorf(log2f(maxv));
            e = fminf(fmaxf(e, -128.0f), 127.0f);
            s_sc[0] = exp2f(-e + 6.0f);     // 2^(-e + (bits-2)), bits=8
            s_sc[1] = exp2f(e - 6.0f);
        }
    }
    __syncthreads();
    const float s = s_sc[0], inv_s = s_sc[1];

    const unsigned stride = NCTA * THREADS;
    for (unsigned i = blockIdx.x * THREADS + threadIdx.x; i < nvec; i += stride)
        y[i] = quant4(x[i], s, inv_s);

    if (blockIdx.x == 0 && threadIdx.x < ntail)
        ys[ntail_base + threadIdx.x] =
            bq_quant_one(xs[ntail_base + threadIdx.x], s, inv_s);
}

extern "C" void kernel_launch(void* const* d_in, const int* in_sizes, int n_in,
                              void* d_out, int out_size) {
    const float* x = (const float*)d_in[0];
    float* y = (float*)d_out;
    unsigned n = (unsigned)in_sizes[0];
    unsigned nvec = n >> 2;
    unsigned ntail_base = nvec << 2;
    unsigned ntail = n - ntail_base;

    bq_max_reduce_kernel<<<NCTA, THREADS>>>(
        (const float4*)x, nvec, x, ntail_base, ntail);

    bq_quantize_kernel<<<NCTA, THREADS>>>(
        (const float4*)x, (float4*)y, nvec, x, y, ntail_base, ntail);
}